// round 13
// baseline (speedup 1.0000x reference)
#include <cuda_runtime.h>
#include <cuda_fp16.h>
#include <cstdint>
#include <math.h>

#define BB 2
#define TT 2048
#define DD 1024
#define HH 16
#define HD 64
#define NTOK (BB*TT)

#define GM 4096
#define GN 1024
#define GK 1024

#define THRESH_C 0.29514f
#define SHARP_C  15.0f
#define NSHARP_L2E (-21.640425613334451f)   // -15 * log2(e)

// ================= low-level helpers =================
#define CP_ASYNC16(dst_u32, src_ptr) \
    asm volatile("cp.async.cg.shared.global [%0], [%1], 16;" \
        :: "r"(dst_u32), "l"(src_ptr) : "memory")
#define CP_COMMIT() asm volatile("cp.async.commit_group;" ::: "memory")
#define CP_WAIT0()  asm volatile("cp.async.wait_group 0;" ::: "memory")

__device__ __forceinline__ uint32_t smem_to_u32(const void* smem_ptr) {
    uint32_t addr;
    asm("{ .reg .u64 tmp; cvta.to.shared.u64 tmp, %1; cvt.u32.u64 %0, tmp; }"
        : "=r"(addr) : "l"(smem_ptr));
    return addr;
}

#define MMA16816(d, a0, a1, a2, a3, b0, b1) \
    asm volatile("mma.sync.aligned.m16n8k16.row.col.f32.f16.f16.f32 " \
        "{%0,%1,%2,%3}, {%4,%5,%6,%7}, {%8,%9}, {%0,%1,%2,%3};" \
        : "+f"((d)[0]), "+f"((d)[1]), "+f"((d)[2]), "+f"((d)[3]) \
        : "r"(a0), "r"(a1), "r"(a2), "r"(a3), "r"(b0), "r"(b1))

#define LDMX4(r0, r1, r2, r3, addr) \
    asm volatile("ldmatrix.sync.aligned.m8n8.x4.shared.b16 {%0,%1,%2,%3}, [%4];" \
        : "=r"(r0), "=r"(r1), "=r"(r2), "=r"(r3) : "r"(addr))

__device__ __forceinline__ uint32_t packh2(float x, float y) {
    __half2 hp = __floats2half2_rn(x, y);
    return *(uint32_t*)&hp;
}

// sigmoid for two fp32 inputs -> packed fp16x2 word (2 MUFU total)
__device__ __forceinline__ uint32_t sig2(float s0, float s1) {
    float z0 = (THRESH_C - s0) * NSHARP_L2E * (-1.0f);   // (t - s)*(-k) = (s-t)*k ... careful
    // we want u = e^{-15(s-t)} = 2^{(t-s)*15*log2e} = 2^{(t-s)*(-NSHARP_L2E)}
    // simpler: z = (t - s) * 21.6404256 ; u = 2^z
    float za = (THRESH_C - s0) * 21.640425613334451f;
    float zb = (THRESH_C - s1) * 21.640425613334451f;
    (void)z0;
    __half2 zz = __floats2half2_rn(za, zb);
    __half2 u  = h2exp2(zz);
    __half2 d  = __hadd2(u, __floats2half2_rn(1.0f, 1.0f));
    __half2 r  = h2rcp(d);
    return *(uint32_t*)&r;
}

// ================= scratch =================
__device__ float g_gateq[BB*HH*TT];
__device__ float g_gatek[BB*HH*TT];

__device__ __half g_qrawh[NTOK*DD];   // raw q (fp16, from qkv epilogue)
__device__ __half g_krawh[NTOK*DD];   // raw k
__device__ __half g_vh[NTOK*DD];      // raw v
__device__ __half g_xh[NTOK*DD];      // raw x fp16 (A of V-proj)
__device__ __half g_xnh[NTOK*DD];     // layernormed x fp16 (A of Q/K-proj)
__device__ __half g_ch[NTOK*DD];      // collapse fp16 (A of out-proj)
__device__ __half g_wqh[DD*DD], g_wkh[DD*DD], g_wvh[DD*DD], g_woh[DD*DD];
__device__ __half g_qbh[NTOK*DD];     // normalized q fp16
__device__ __half g_kbh[NTOK*DD];     // normalized k fp16
__device__ __half g_vth[BB*DD*TT];    // gk*V transposed fp16

// ================= LayerNorm fused with fp16 conversions =================
__global__ __launch_bounds__(256) void ln_kernel(const float* __restrict__ x,
                                                 const float* __restrict__ w,
                                                 const float* __restrict__ b) {
    int row = blockIdx.x;
    int tid = threadIdx.x;
    const float4* xr = (const float4*)(x + (size_t)row * DD);
    float4 v = xr[tid];
    float s  = v.x + v.y + v.z + v.w;
    float sq = v.x*v.x + v.y*v.y + v.z*v.z + v.w*v.w;
    #pragma unroll
    for (int o = 16; o > 0; o >>= 1) {
        s  += __shfl_xor_sync(0xffffffffu, s,  o);
        sq += __shfl_xor_sync(0xffffffffu, sq, o);
    }
    __shared__ float ss[8], ssq[8];
    int wid = tid >> 5, lid = tid & 31;
    if (lid == 0) { ss[wid] = s; ssq[wid] = sq; }
    __syncthreads();
    float ts = 0.f, tsq = 0.f;
    #pragma unroll
    for (int i = 0; i < 8; i++) { ts += ss[i]; tsq += ssq[i]; }
    float mu  = ts * (1.0f/DD);
    float var = tsq * (1.0f/DD) - mu*mu;
    float inv = rsqrtf(var + 1e-5f);
    float4 wv = ((const float4*)w)[tid];
    float4 bv = ((const float4*)b)[tid];
    float4 o;
    o.x = (v.x - mu) * inv * wv.x + bv.x;
    o.y = (v.y - mu) * inv * wv.y + bv.y;
    o.z = (v.z - mu) * inv * wv.z + bv.z;
    o.w = (v.w - mu) * inv * wv.w + bv.w;

    int i4 = row * (DD/4) + tid;
    {
        uint2 hw = { packh2(v.x, v.y), packh2(v.z, v.w) };
        ((uint2*)g_xh)[i4] = hw;
    }
    {
        uint2 hw = { packh2(o.x, o.y), packh2(o.z, o.w) };
        ((uint2*)g_xnh)[i4] = hw;
    }
}

// ===== all 4 weights: W[K,N] -> Wt[N,K] transpose, fp16 (z-indexed) =====
__global__ __launch_bounds__(256) void tsplit4_kernel(const float* __restrict__ W0,
                                                      const float* __restrict__ W1,
                                                      const float* __restrict__ W2,
                                                      const float* __restrict__ W3) {
    __shared__ float tile[32][33];
    const float* W;
    __half* th;
    switch (blockIdx.z) {
        case 0: W = W0; th = g_wqh; break;
        case 1: W = W1; th = g_wkh; break;
        case 2: W = W2; th = g_wvh; break;
        default: W = W3; th = g_woh; break;
    }
    int bx = blockIdx.x * 32;
    int by = blockIdx.y * 32;
    int tx = threadIdx.x & 31;
    int ty = threadIdx.x >> 5;
    #pragma unroll
    for (int i = 0; i < 4; i++) {
        int k = by + ty + i*8;
        tile[ty + i*8][tx] = W[(size_t)k * DD + bx + tx];
    }
    __syncthreads();
    #pragma unroll
    for (int i = 0; i < 4; i++) {
        int n = bx + ty + i*8;
        int k = by + tx;
        th[(size_t)n * DD + k] = __float2half_rn(tile[tx][ty + i*8]);
    }
}

// ========== V[b][t][d] (fp16) -> Vt[b*DD+d][t], gate_k premultiplied, fp16 ==========
__global__ __launch_bounds__(256) void vtsplit_kernel(const __half* __restrict__ V,
                                                      const float* __restrict__ gatek,
                                                      __half* __restrict__ th) {
    __shared__ float tile[32][33];
    int b  = blockIdx.z;
    int t0 = blockIdx.x * 32;
    int d0 = blockIdx.y * 32;
    int tx = threadIdx.x & 31;
    int ty = threadIdx.x >> 5;
    #pragma unroll
    for (int i = 0; i < 4; i++) {
        int tt = t0 + ty + i*8;
        tile[ty + i*8][tx] = __half2float(V[((size_t)(b*TT + tt)) * DD + d0 + tx]);
    }
    __syncthreads();
    int h = d0 >> 6;
    float gk = gatek[((size_t)(b*HH + h)) * TT + t0 + tx];
    #pragma unroll
    for (int i = 0; i < 4; i++) {
        int d = d0 + ty + i*8;
        int tt = t0 + tx;
        th[((size_t)(b*DD + d)) * TT + tt] = __float2half_rn(tile[tx][ty + i*8] * gk);
    }
}

// ================= mma.sync GEMM body, BK=64, 2-stage cp.async pipeline =================
#define PAD_K 72
#define ARR_BYTES (128*PAD_K*2)
#define STAGE_BYTES (2*ARR_BYTES)
#define GEMM_SMEM_BYTES (2*STAGE_BYTES)      // 73728 -> 3 CTAs/SM resident

__device__ __forceinline__ void gemm_load_stage(uint32_t sm_u32, int stage,
        const __half* __restrict__ Ah, const __half* __restrict__ Bh,
        int m0, int n0, int k0, int t) {
    uint32_t sbase = sm_u32 + (uint32_t)stage * STAGE_BYTES;
    #pragma unroll
    for (int o = 0; o < 4; o++) {
        int linear = t + o*256;
        int r  = linear >> 3;
        int c8 = linear & 7;
        uint32_t soff = (uint32_t)(r*(PAD_K*2) + c8*16);
        size_t goffA = (size_t)(m0 + r) * GK + k0 + c8*8;
        size_t goffB = (size_t)(n0 + r) * GK + k0 + c8*8;
        CP_ASYNC16(sbase +             soff, Ah + goffA);
        CP_ASYNC16(sbase + ARR_BYTES + soff, Bh + goffB);
    }
}

// HALF_OUT: write packed fp16 pairs; else fp32 (+bias)
template<bool HALF_OUT>
__device__ __forceinline__ void gemm_body(uint32_t sm_u32,
        const __half* __restrict__ Ah, const __half* __restrict__ Bh,
        void* __restrict__ Cv, const float* __restrict__ bias,
        int m0, int n0, int t) {
    int wid = t >> 5, lane = t & 31;
    int wm = wid & 1;
    int wn = wid >> 1;
    int g  = lane >> 2;
    int tq = lane & 3;

    float acc[4][4][4];
    #pragma unroll
    for (int mi = 0; mi < 4; mi++)
        #pragma unroll
        for (int ni = 0; ni < 4; ni++)
            #pragma unroll
            for (int r = 0; r < 4; r++) acc[mi][ni][r] = 0.f;

    int a_rsel = lane & 15;
    int a_ksel = (lane >> 4) * 8;
    int b_row  = lane & 7;
    int b_msel = (lane >> 4);
    int b_ksel = ((lane >> 3) & 1) * 8;

    const int NIT = GK / 64;
    gemm_load_stage(sm_u32, 0, Ah, Bh, m0, n0, 0, t);
    CP_COMMIT();

    for (int it = 0; it < NIT; it++) {
        CP_WAIT0();
        __syncthreads();
        if (it + 1 < NIT) {
            gemm_load_stage(sm_u32, (it+1) & 1, Ah, Bh, m0, n0, (it+1)*64, t);
            CP_COMMIT();
        }
        uint32_t S   = sm_u32 + (uint32_t)(it & 1) * STAGE_BYTES;
        uint32_t uAh = S;
        uint32_t uBh = S + ARR_BYTES;

        #pragma unroll
        for (int kk = 0; kk < 64; kk += 16) {
            uint32_t ah[4][4];
            #pragma unroll
            for (int mi = 0; mi < 4; mi++) {
                uint32_t off = (uint32_t)(((wm*64 + mi*16 + a_rsel) * PAD_K + kk + a_ksel) * 2);
                LDMX4(ah[mi][0], ah[mi][1], ah[mi][2], ah[mi][3], uAh + off);
            }
            uint32_t bh[4][2];
            #pragma unroll
            for (int np = 0; np < 2; np++) {
                uint32_t off = (uint32_t)(((wn*32 + (np*2 + b_msel)*8 + b_row) * PAD_K + kk + b_ksel) * 2);
                uint32_t r0, r1, r2, r3;
                LDMX4(r0, r1, r2, r3, uBh + off);
                bh[np*2][0]=r0; bh[np*2][1]=r1; bh[np*2+1][0]=r2; bh[np*2+1][1]=r3;
            }
            #pragma unroll
            for (int ni = 0; ni < 4; ni++)
                #pragma unroll
                for (int mi = 0; mi < 4; mi++)
                    MMA16816(acc[mi][ni], ah[mi][0], ah[mi][1], ah[mi][2], ah[mi][3], bh[ni][0], bh[ni][1]);
        }
    }

    #pragma unroll
    for (int mi = 0; mi < 4; mi++) {
        int row = m0 + wm*64 + mi*16 + g;
        #pragma unroll
        for (int ni = 0; ni < 4; ni++) {
            int col = n0 + wn*32 + ni*8 + tq*2;
            if (HALF_OUT) {
                __half* Ch = (__half*)Cv;
                *(uint32_t*)(Ch + (size_t)row * GN + col)     = packh2(acc[mi][ni][0], acc[mi][ni][1]);
                *(uint32_t*)(Ch + (size_t)(row+8) * GN + col) = packh2(acc[mi][ni][2], acc[mi][ni][3]);
            } else {
                float* C = (float*)Cv;
                float b0 = 0.f, b1 = 0.f;
                if (bias) { b0 = bias[col]; b1 = bias[col+1]; }
                float2 v0 = { acc[mi][ni][0] + b0, acc[mi][ni][1] + b1 };
                float2 v1 = { acc[mi][ni][2] + b0, acc[mi][ni][3] + b1 };
                *(float2*)(C + (size_t)row * GN + col)       = v0;
                *(float2*)(C + (size_t)(row+8) * GN + col)   = v1;
            }
        }
    }
}

// ---- fused Q/K/V projection: z selects (A, B, C); fp16 outputs ----
__global__ __launch_bounds__(256) void qkv_gemm() {
    extern __shared__ __half smb[];
    uint32_t sm_u32 = smem_to_u32(smb);
    const __half *Ah, *Bh;
    __half* C;
    switch (blockIdx.z) {
        case 0:  Ah = g_xnh; Bh = g_wqh; C = g_qrawh; break;
        case 1:  Ah = g_xnh; Bh = g_wkh; C = g_krawh; break;
        default: Ah = g_xh;  Bh = g_wvh; C = g_vh;    break;
    }
    gemm_body<true>(sm_u32, Ah, Bh, C, nullptr, blockIdx.y * 128, blockIdx.x * 128, threadIdx.x);
}

// ---- output projection (fp32 + bias) ----
__global__ __launch_bounds__(256) void out_gemm(float* __restrict__ C,
                                                const float* __restrict__ bias) {
    extern __shared__ __half smb[];
    uint32_t sm_u32 = smem_to_u32(smb);
    gemm_body<false>(sm_u32, g_ch, g_woh, C, bias, blockIdx.y * 128, blockIdx.x * 128, threadIdx.x);
}

// ======== l2-normalize + gate for BOTH q and k (y-indexed); fp16 in/out ========
__global__ __launch_bounds__(256) void norm_gate2_kernel(const float* __restrict__ gqv,
                                                         const float* __restrict__ gkv) {
    bool isq = (blockIdx.y == 0);
    const __half* raw = isq ? g_qrawh : g_krawh;
    const float* g    = isq ? gqv : gkv;
    __half* oh        = isq ? g_qbh : g_kbh;
    float* gate       = isq ? g_gateq : g_gatek;

    int task = blockIdx.x * 8 + (threadIdx.x >> 5);
    int lane = threadIdx.x & 31;
    int token = task >> 4;
    int h = task & 15;
    size_t base = (size_t)token * DD + h * HD;
    uint32_t vw = ((const uint32_t*)(raw + base))[lane];
    __half2 vh = *(__half2*)&vw;
    float2 v = __half22float2(vh);
    float sq = v.x*v.x + v.y*v.y;
    #pragma unroll
    for (int o = 16; o > 0; o >>= 1) sq += __shfl_xor_sync(0xffffffffu, sq, o);
    float nrm = sqrtf(sq);
    float inv = 1.0f / fmaxf(nrm, 1e-12f);
    float nx = v.x * inv, ny = v.y * inv;
    ((uint32_t*)(oh + base))[lane] = packh2(nx, ny);
    float2 gv = ((const float2*)g)[lane];
    float gp = nx*gv.x + ny*gv.y;
    #pragma unroll
    for (int o = 16; o > 0; o >>= 1) gp += __shfl_xor_sync(0xffffffffu, gp, o);
    if (lane == 0) {
        int b = token / TT, t = token % TT;
        gate[((size_t)(b*HH + h)) * TT + t] = gp;
    }
}

// ======== attention: mma.sync fp16, 2-stage x 128-s stages ========
#define HSTG 18432
#define ATTN_STG (2*HSTG)
#define ATTN_SMEM (2*ATTN_STG)      // 73728 -> 3 CTAs/SM

__device__ __forceinline__ void attn_load_half(uint32_t hbase,
        int b, int h, int s0, int t,
        const __half* __restrict__ Kh, const __half* __restrict__ Vh) {
    int row_lo = t >> 3;
    int c = t & 7;
    #pragma unroll
    for (int i = 0; i < 4; i++) {
        int arr = i >> 1;
        int row = ((i & 1) << 5) + row_lo;
        uint32_t dst = hbase + (uint32_t)(arr*9216 + row*144 + c*16);
        const __half* src = (arr == 0)
            ? Kh + ((size_t)(b*TT + s0 + row))*DD + h*64 + c*8
            : Vh + ((size_t)(b*DD + h*64 + row))*TT + s0 + c*8;
        CP_ASYNC16(dst, src);
    }
}

__global__ __launch_bounds__(256) void attn_mma_kernel(
        const __half* __restrict__ Qh,
        const __half* __restrict__ Kh, const __half* __restrict__ Vh,
        const float* __restrict__ gateq) {
    extern __shared__ char smc[];
    uint32_t sb = smem_to_u32(smc);
    int t = threadIdx.x;
    int w = t >> 5, lane = t & 31;
    int g = lane >> 2, tq = lane & 3;
    int bh = blockIdx.y;
    int b = bh >> 4, h = bh & 15;
    int t0 = blockIdx.x * 128;
    int trow = t0 + w*16 + g;

    int b_row  = lane & 7;
    int b_msel = (lane >> 4);
    int b_ksel = ((lane >> 3) & 1) * 8;

    uint32_t aqh[4][4];
    {
        size_t r0 = ((size_t)(b*TT + trow))*DD + h*64;
        size_t r8 = r0 + 8*(size_t)DD;
        #pragma unroll
        for (int kq = 0; kq < 4; kq++) {
            int c = kq*16 + tq*2;
            aqh[kq][0] = *(const uint32_t*)(Qh + r0 + c);
            aqh[kq][1] = *(const uint32_t*)(Qh + r8 + c);
            aqh[kq][2] = *(const uint32_t*)(Qh + r0 + c + 8);
            aqh[kq][3] = *(const uint32_t*)(Qh + r8 + c + 8);
        }
    }
    float gq0 = gateq[(size_t)bh*TT + trow];
    float gq1 = gateq[(size_t)bh*TT + trow + 8];

    float cacc[8][4];
    #pragma unroll
    for (int di = 0; di < 8; di++)
        #pragma unroll
        for (int r = 0; r < 4; r++) cacc[di][r] = 0.f;

    const int NCH = TT / 128;
    attn_load_half(sb,        b, h, 0,  t, Kh, Vh);
    attn_load_half(sb + HSTG, b, h, 64, t, Kh, Vh);
    CP_COMMIT();

    for (int ic = 0; ic < NCH; ic++) {
        CP_WAIT0();
        __syncthreads();
        if (ic + 1 < NCH) {
            uint32_t nbase = sb + (uint32_t)((ic+1) & 1) * ATTN_STG;
            attn_load_half(nbase,        b, h, (ic+1)*128,      t, Kh, Vh);
            attn_load_half(nbase + HSTG, b, h, (ic+1)*128 + 64, t, Kh, Vh);
            CP_COMMIT();
        }
        uint32_t stg = sb + (uint32_t)(ic & 1) * ATTN_STG;

        #pragma unroll
        for (int half = 0; half < 2; half++) {
            uint32_t uKh = stg + (uint32_t)half * HSTG;
            uint32_t uVh = uKh + 9216;

            // ---- GEMM1: S = Q . K^T ----
            float sacc[8][4];
            #pragma unroll
            for (int si = 0; si < 8; si++)
                #pragma unroll
                for (int r = 0; r < 4; r++) sacc[si][r] = 0.f;

            #pragma unroll
            for (int kk = 0; kk < 4; kk++) {
                uint32_t kfh[4][4];
                #pragma unroll
                for (int sp = 0; sp < 4; sp++) {
                    uint32_t off = (uint32_t)(((sp*2 + b_msel)*8 + b_row)*144 + (kk*16 + b_ksel)*2);
                    LDMX4(kfh[sp][0], kfh[sp][1], kfh[sp][2], kfh[sp][3], uKh + off);
                }
                #pragma unroll
                for (int sp = 0; sp < 4; sp++) {
                    MMA16816(sacc[2*sp],   aqh[kk][0], aqh[kk][1], aqh[kk][2], aqh[kk][3], kfh[sp][0], kfh[sp][1]);
                    MMA16816(sacc[2*sp+1], aqh[kk][0], aqh[kk][1], aqh[kk][2], aqh[kk][3], kfh[sp][2], kfh[sp][3]);
                }
            }

            // ---- modulation: half2 sigmoid (2 MUFU per 2 values) ----
            uint32_t mh[4][4];
            #pragma unroll
            for (int j = 0; j < 4; j++) {
                #pragma unroll
                for (int hv = 0; hv < 2; hv++) {
                    int si = 2*j + hv;
                    mh[j][hv*2 + 0] = sig2(sacc[si][0], sacc[si][1]);
                    mh[j][hv*2 + 1] = sig2(sacc[si][2], sacc[si][3]);
                }
            }

            // ---- GEMM2: C += M . (gk*V) ----
            #pragma unroll
            for (int j = 0; j < 4; j++) {
                uint32_t vfh[4][4];
                #pragma unroll
                for (int dp = 0; dp < 4; dp++) {
                    uint32_t off = (uint32_t)(((dp*2 + b_msel)*8 + b_row)*144 + (j*16 + b_ksel)*2);
                    LDMX4(vfh[dp][0], vfh[dp][1], vfh[dp][2], vfh[dp][3], uVh + off);
                }
                #pragma unroll
                for (int dp = 0; dp < 4; dp++) {
                    MMA16816(cacc[2*dp],   mh[j][0], mh[j][1], mh[j][2], mh[j][3], vfh[dp][0], vfh[dp][1]);
                    MMA16816(cacc[2*dp+1], mh[j][0], mh[j][1], mh[j][2], mh[j][3], vfh[dp][2], vfh[dp][3]);
                }
            }
        }
    }

    // epilogue: apply gq, emit fp16 collapse
    size_t obase = ((size_t)(b*TT + trow))*DD + h*64;
    #pragma unroll
    for (int di = 0; di < 8; di++) {
        int col = di*8 + tq*2;
        float c00 = cacc[di][0]*gq0, c01 = cacc[di][1]*gq0;
        float c10 = cacc[di][2]*gq1, c11 = cacc[di][3]*gq1;
        *(uint32_t*)(g_ch + obase + col)                = packh2(c00, c01);
        *(uint32_t*)(g_ch + obase + 8*(size_t)DD + col) = packh2(c10, c11);
    }
}

// ================= launch =================
extern "C" void kernel_launch(void* const* d_in, const int* in_sizes, int n_in,
                              void* d_out, int out_size) {
    const float* x    = (const float*)d_in[0];
    const float* Wq   = (const float*)d_in[1];
    const float* Wk   = (const float*)d_in[2];
    const float* Wv   = (const float*)d_in[3];
    const float* gq   = (const float*)d_in[4];
    const float* gk   = (const float*)d_in[5];
    const float* Wo   = (const float*)d_in[6];
    const float* bo   = (const float*)d_in[7];
    const float* ln_w = (const float*)d_in[8];
    const float* ln_b = (const float*)d_in[9];
    float* out = (float*)d_out;

    float *p_gq, *p_gk;
    cudaGetSymbolAddress((void**)&p_gq, g_gateq);
    cudaGetSymbolAddress((void**)&p_gk, g_gatek);

    __half *p_vh, *p_qbh, *p_kbh, *p_vth;
    cudaGetSymbolAddress((void**)&p_vh,  g_vh);
    cudaGetSymbolAddress((void**)&p_qbh, g_qbh);
    cudaGetSymbolAddress((void**)&p_kbh, g_kbh);
    cudaGetSymbolAddress((void**)&p_vth, g_vth);

    cudaFuncSetAttribute(qkv_gemm, cudaFuncAttributeMaxDynamicSharedMemorySize, GEMM_SMEM_BYTES);
    cudaFuncSetAttribute(out_gemm, cudaFuncAttributeMaxDynamicSharedMemorySize, GEMM_SMEM_BYTES);
    cudaFuncSetAttribute(attn_mma_kernel, cudaFuncAttributeMaxDynamicSharedMemorySize, ATTN_SMEM);

    // 1. LayerNorm + fp16 conversions
    ln_kernel<<<NTOK, 256>>>(x, ln_w, ln_b);

    // 2. weight transpose (fp16), z-indexed
    tsplit4_kernel<<<dim3(DD/32, DD/32, 4), 256>>>(Wq, Wk, Wv, Wo);

    // 3. fused QKV projections (fp16 outputs)
    qkv_gemm<<<dim3(GN/128, GM/128, 3), 256, GEMM_SMEM_BYTES>>>();

    // 4. normalize + gates (fp16 in); V transpose (fp16 in)
    norm_gate2_kernel<<<dim3((NTOK*HH)/8, 2), 256>>>(gq, gk);
    vtsplit_kernel<<<dim3(TT/32, DD/32, BB), 256>>>(p_vh, p_gk, p_vth);

    // 5. attention (half2 sigmoid)
    attn_mma_kernel<<<dim3(TT/128, BB*HH), 256, ATTN_SMEM>>>(
        p_qbh, p_kbh, p_vth, p_gq);

    // 6. output projection
    out_gemm<<<dim3(GN/128, GM/128), 256, GEMM_SMEM_BYTES>>>(out, bo);
}

// round 15
// speedup vs baseline: 1.0135x; 1.0135x over previous
#include <cuda_runtime.h>
#include <cuda_fp16.h>
#include <cstdint>
#include <math.h>

#define BB 2
#define TT 2048
#define DD 1024
#define HH 16
#define HD 64
#define NTOK (BB*TT)

#define GM 4096
#define GN 1024
#define GK 1024

#define THRESH_C 0.29514f
#define SHARP_C  15.0f

// ================= low-level helpers =================
#define CP_ASYNC16(dst_u32, src_ptr) \
    asm volatile("cp.async.cg.shared.global [%0], [%1], 16;" \
        :: "r"(dst_u32), "l"(src_ptr) : "memory")
#define CP_COMMIT() asm volatile("cp.async.commit_group;" ::: "memory")
#define CP_WAIT0()  asm volatile("cp.async.wait_group 0;" ::: "memory")

__device__ __forceinline__ uint32_t smem_to_u32(const void* smem_ptr) {
    uint32_t addr;
    asm("{ .reg .u64 tmp; cvta.to.shared.u64 tmp, %1; cvt.u32.u64 %0, tmp; }"
        : "=r"(addr) : "l"(smem_ptr));
    return addr;
}

#define MMA16816(d, a0, a1, a2, a3, b0, b1) \
    asm volatile("mma.sync.aligned.m16n8k16.row.col.f32.f16.f16.f32 " \
        "{%0,%1,%2,%3}, {%4,%5,%6,%7}, {%8,%9}, {%0,%1,%2,%3};" \
        : "+f"((d)[0]), "+f"((d)[1]), "+f"((d)[2]), "+f"((d)[3]) \
        : "r"(a0), "r"(a1), "r"(a2), "r"(a3), "r"(b0), "r"(b1))

#define LDMX4(r0, r1, r2, r3, addr) \
    asm volatile("ldmatrix.sync.aligned.m8n8.x4.shared.b16 {%0,%1,%2,%3}, [%4];" \
        : "=r"(r0), "=r"(r1), "=r"(r2), "=r"(r3) : "r"(addr))

__device__ __forceinline__ uint32_t packh2(float x, float y) {
    __half2 hp = __floats2half2_rn(x, y);
    return *(uint32_t*)&hp;
}

// ================= scratch =================
__device__ float g_gateq[BB*HH*TT];
__device__ float g_gatek[BB*HH*TT];

__device__ __half g_qrawh[NTOK*DD];   // raw q (fp16, from qkv epilogue)
__device__ __half g_krawh[NTOK*DD];   // raw k
__device__ __half g_vh[NTOK*DD];      // raw v
__device__ __half g_xh[NTOK*DD];      // raw x fp16 (A of V-proj)
__device__ __half g_xnh[NTOK*DD];     // layernormed x fp16 (A of Q/K-proj)
__device__ __half g_ch[NTOK*DD];      // collapse fp16 (A of out-proj)
__device__ __half g_wqh[DD*DD], g_wkh[DD*DD], g_wvh[DD*DD], g_woh[DD*DD];
__device__ __half g_qbh[NTOK*DD];     // normalized q fp16
__device__ __half g_kbh[NTOK*DD];     // normalized k fp16
__device__ __half g_vth[BB*DD*TT];    // gk*V transposed fp16

// ================= LayerNorm fused with fp16 conversions =================
__global__ __launch_bounds__(256) void ln_kernel(const float* __restrict__ x,
                                                 const float* __restrict__ w,
                                                 const float* __restrict__ b) {
    int row = blockIdx.x;
    int tid = threadIdx.x;
    const float4* xr = (const float4*)(x + (size_t)row * DD);
    float4 v = xr[tid];
    float s  = v.x + v.y + v.z + v.w;
    float sq = v.x*v.x + v.y*v.y + v.z*v.z + v.w*v.w;
    #pragma unroll
    for (int o = 16; o > 0; o >>= 1) {
        s  += __shfl_xor_sync(0xffffffffu, s,  o);
        sq += __shfl_xor_sync(0xffffffffu, sq, o);
    }
    __shared__ float ss[8], ssq[8];
    int wid = tid >> 5, lid = tid & 31;
    if (lid == 0) { ss[wid] = s; ssq[wid] = sq; }
    __syncthreads();
    float ts = 0.f, tsq = 0.f;
    #pragma unroll
    for (int i = 0; i < 8; i++) { ts += ss[i]; tsq += ssq[i]; }
    float mu  = ts * (1.0f/DD);
    float var = tsq * (1.0f/DD) - mu*mu;
    float inv = rsqrtf(var + 1e-5f);
    float4 wv = ((const float4*)w)[tid];
    float4 bv = ((const float4*)b)[tid];
    float4 o;
    o.x = (v.x - mu) * inv * wv.x + bv.x;
    o.y = (v.y - mu) * inv * wv.y + bv.y;
    o.z = (v.z - mu) * inv * wv.z + bv.z;
    o.w = (v.w - mu) * inv * wv.w + bv.w;

    int i4 = row * (DD/4) + tid;
    {
        uint2 hw = { packh2(v.x, v.y), packh2(v.z, v.w) };
        ((uint2*)g_xh)[i4] = hw;
    }
    {
        uint2 hw = { packh2(o.x, o.y), packh2(o.z, o.w) };
        ((uint2*)g_xnh)[i4] = hw;
    }
}

// ===== weights: W[K,N] -> Wt[N,K] transpose, fp16, vectorized stores =====
// tile: 64 k-rows x 32 n-cols.  Output rows are 64 halves = 128B coalesced.
__global__ __launch_bounds__(256) void tsplit4_kernel(const float* __restrict__ W0,
                                                      const float* __restrict__ W1,
                                                      const float* __restrict__ W2,
                                                      const float* __restrict__ W3) {
    __shared__ float tile[64][33];
    const float* W;
    __half* th;
    switch (blockIdx.z) {
        case 0: W = W0; th = g_wqh; break;
        case 1: W = W1; th = g_wkh; break;
        case 2: W = W2; th = g_wvh; break;
        default: W = W3; th = g_woh; break;
    }
    int bx = blockIdx.x * 32;   // n block
    int by = blockIdx.y * 64;   // k block
    int tx = threadIdx.x & 31;
    int ty = threadIdx.x >> 5;  // 0..7
    #pragma unroll
    for (int i = 0; i < 8; i++) {
        int kr = ty + i*8;      // 0..63
        tile[kr][tx] = W[(size_t)(by + kr) * DD + bx + tx];
    }
    __syncthreads();
    #pragma unroll
    for (int j = 0; j < 4; j++) {
        int n = ty + j*8;       // 0..31
        float a = tile[2*tx][n];
        float b = tile[2*tx + 1][n];
        *(uint32_t*)(th + (size_t)(bx + n) * DD + by + 2*tx) = packh2(a, b);
    }
}

// ========== V[b][t][d] (fp16) -> Vt[b*DD+d][t], gate_k premultiplied, fp16 ==========
__global__ __launch_bounds__(256) void vtsplit_kernel(const __half* __restrict__ V,
                                                      const float* __restrict__ gatek,
                                                      __half* __restrict__ th) {
    __shared__ float tile[32][33];
    int b  = blockIdx.z;
    int t0 = blockIdx.x * 32;
    int d0 = blockIdx.y * 32;
    int tx = threadIdx.x & 31;
    int ty = threadIdx.x >> 5;
    #pragma unroll
    for (int i = 0; i < 4; i++) {
        int tt = t0 + ty + i*8;
        tile[ty + i*8][tx] = __half2float(V[((size_t)(b*TT + tt)) * DD + d0 + tx]);
    }
    __syncthreads();
    int h = d0 >> 6;
    float gk = gatek[((size_t)(b*HH + h)) * TT + t0 + tx];
    #pragma unroll
    for (int i = 0; i < 4; i++) {
        int d = d0 + ty + i*8;
        int tt = t0 + tx;
        th[((size_t)(b*DD + d)) * TT + tt] = __float2half_rn(tile[tx][ty + i*8] * gk);
    }
}

// ================= mma.sync GEMM body, BK=64, 2-stage cp.async pipeline =================
#define PAD_K 72
#define ARR_BYTES (128*PAD_K*2)
#define STAGE_BYTES (2*ARR_BYTES)
#define GEMM_SMEM_BYTES (2*STAGE_BYTES)      // 73728 -> 3 CTAs/SM resident

__device__ __forceinline__ void gemm_load_stage(uint32_t sm_u32, int stage,
        const __half* __restrict__ Ah, const __half* __restrict__ Bh,
        int m0, int n0, int k0, int t) {
    uint32_t sbase = sm_u32 + (uint32_t)stage * STAGE_BYTES;
    #pragma unroll
    for (int o = 0; o < 4; o++) {
        int linear = t + o*256;
        int r  = linear >> 3;
        int c8 = linear & 7;
        uint32_t soff = (uint32_t)(r*(PAD_K*2) + c8*16);
        size_t goffA = (size_t)(m0 + r) * GK + k0 + c8*8;
        size_t goffB = (size_t)(n0 + r) * GK + k0 + c8*8;
        CP_ASYNC16(sbase +             soff, Ah + goffA);
        CP_ASYNC16(sbase + ARR_BYTES + soff, Bh + goffB);
    }
}

// HALF_OUT: write packed fp16 pairs; else fp32 (+bias)
template<bool HALF_OUT>
__device__ __forceinline__ void gemm_body(uint32_t sm_u32,
        const __half* __restrict__ Ah, const __half* __restrict__ Bh,
        void* __restrict__ Cv, const float* __restrict__ bias,
        int m0, int n0, int t) {
    int wid = t >> 5, lane = t & 31;
    int wm = wid & 1;
    int wn = wid >> 1;
    int g  = lane >> 2;
    int tq = lane & 3;

    float acc[4][4][4];
    #pragma unroll
    for (int mi = 0; mi < 4; mi++)
        #pragma unroll
        for (int ni = 0; ni < 4; ni++)
            #pragma unroll
            for (int r = 0; r < 4; r++) acc[mi][ni][r] = 0.f;

    int a_rsel = lane & 15;
    int a_ksel = (lane >> 4) * 8;
    int b_row  = lane & 7;
    int b_msel = (lane >> 4);
    int b_ksel = ((lane >> 3) & 1) * 8;

    const int NIT = GK / 64;
    gemm_load_stage(sm_u32, 0, Ah, Bh, m0, n0, 0, t);
    CP_COMMIT();

    for (int it = 0; it < NIT; it++) {
        CP_WAIT0();
        __syncthreads();
        if (it + 1 < NIT) {
            gemm_load_stage(sm_u32, (it+1) & 1, Ah, Bh, m0, n0, (it+1)*64, t);
            CP_COMMIT();
        }
        uint32_t S   = sm_u32 + (uint32_t)(it & 1) * STAGE_BYTES;
        uint32_t uAh = S;
        uint32_t uBh = S + ARR_BYTES;

        #pragma unroll
        for (int kk = 0; kk < 64; kk += 16) {
            uint32_t ah[4][4];
            #pragma unroll
            for (int mi = 0; mi < 4; mi++) {
                uint32_t off = (uint32_t)(((wm*64 + mi*16 + a_rsel) * PAD_K + kk + a_ksel) * 2);
                LDMX4(ah[mi][0], ah[mi][1], ah[mi][2], ah[mi][3], uAh + off);
            }
            uint32_t bh[4][2];
            #pragma unroll
            for (int np = 0; np < 2; np++) {
                uint32_t off = (uint32_t)(((wn*32 + (np*2 + b_msel)*8 + b_row) * PAD_K + kk + b_ksel) * 2);
                uint32_t r0, r1, r2, r3;
                LDMX4(r0, r1, r2, r3, uBh + off);
                bh[np*2][0]=r0; bh[np*2][1]=r1; bh[np*2+1][0]=r2; bh[np*2+1][1]=r3;
            }
            #pragma unroll
            for (int ni = 0; ni < 4; ni++)
                #pragma unroll
                for (int mi = 0; mi < 4; mi++)
                    MMA16816(acc[mi][ni], ah[mi][0], ah[mi][1], ah[mi][2], ah[mi][3], bh[ni][0], bh[ni][1]);
        }
    }

    #pragma unroll
    for (int mi = 0; mi < 4; mi++) {
        int row = m0 + wm*64 + mi*16 + g;
        #pragma unroll
        for (int ni = 0; ni < 4; ni++) {
            int col = n0 + wn*32 + ni*8 + tq*2;
            if (HALF_OUT) {
                __half* Ch = (__half*)Cv;
                *(uint32_t*)(Ch + (size_t)row * GN + col)     = packh2(acc[mi][ni][0], acc[mi][ni][1]);
                *(uint32_t*)(Ch + (size_t)(row+8) * GN + col) = packh2(acc[mi][ni][2], acc[mi][ni][3]);
            } else {
                float* C = (float*)Cv;
                float b0 = 0.f, b1 = 0.f;
                if (bias) { b0 = bias[col]; b1 = bias[col+1]; }
                float2 v0 = { acc[mi][ni][0] + b0, acc[mi][ni][1] + b1 };
                float2 v1 = { acc[mi][ni][2] + b0, acc[mi][ni][3] + b1 };
                *(float2*)(C + (size_t)row * GN + col)       = v0;
                *(float2*)(C + (size_t)(row+8) * GN + col)   = v1;
            }
        }
    }
}

// ---- fused Q/K/V projection: z selects (A, B, C); fp16 outputs ----
__global__ __launch_bounds__(256) void qkv_gemm() {
    extern __shared__ __half smb[];
    uint32_t sm_u32 = smem_to_u32(smb);
    const __half *Ah, *Bh;
    __half* C;
    switch (blockIdx.z) {
        case 0:  Ah = g_xnh; Bh = g_wqh; C = g_qrawh; break;
        case 1:  Ah = g_xnh; Bh = g_wkh; C = g_krawh; break;
        default: Ah = g_xh;  Bh = g_wvh; C = g_vh;    break;
    }
    gemm_body<true>(sm_u32, Ah, Bh, C, nullptr, blockIdx.y * 128, blockIdx.x * 128, threadIdx.x);
}

// ---- output projection (fp32 + bias) ----
__global__ __launch_bounds__(256) void out_gemm(float* __restrict__ C,
                                                const float* __restrict__ bias) {
    extern __shared__ __half smb[];
    uint32_t sm_u32 = smem_to_u32(smb);
    gemm_body<false>(sm_u32, g_ch, g_woh, C, bias, blockIdx.y * 128, blockIdx.x * 128, threadIdx.x);
}

// ======== l2-normalize + gate, single-pass dual reduction; fp16 in/out ========
__global__ __launch_bounds__(256) void norm_gate2_kernel(const float* __restrict__ gqv,
                                                         const float* __restrict__ gkv) {
    bool isq = (blockIdx.y == 0);
    const __half* raw = isq ? g_qrawh : g_krawh;
    const float* g    = isq ? gqv : gkv;
    __half* oh        = isq ? g_qbh : g_kbh;
    float* gate       = isq ? g_gateq : g_gatek;

    int task = blockIdx.x * 8 + (threadIdx.x >> 5);
    int lane = threadIdx.x & 31;
    int token = task >> 4;
    int h = task & 15;
    size_t base = (size_t)token * DD + h * HD;
    uint32_t vw = ((const uint32_t*)(raw + base))[lane];
    __half2 vh = *(__half2*)&vw;
    float2 v = __half22float2(vh);
    float2 gv = ((const float2*)g)[lane];
    float sq = v.x*v.x + v.y*v.y;
    float rg = v.x*gv.x + v.y*gv.y;
    #pragma unroll
    for (int o = 16; o > 0; o >>= 1) {
        sq += __shfl_xor_sync(0xffffffffu, sq, o);
        rg += __shfl_xor_sync(0xffffffffu, rg, o);
    }
    float inv = 1.0f / fmaxf(sqrtf(sq), 1e-12f);
    ((uint32_t*)(oh + base))[lane] = packh2(v.x * inv, v.y * inv);
    if (lane == 0) {
        int b = token / TT, t = token % TT;
        gate[((size_t)(b*HH + h)) * TT + t] = rg * inv;
    }
}

// ======== attention: mma.sync fp16, 2-stage x 128-s stages ========
#define HSTG 18432
#define ATTN_STG (2*HSTG)
#define ATTN_SMEM (2*ATTN_STG)      // 73728 -> 3 CTAs/SM

__device__ __forceinline__ void attn_load_half(uint32_t hbase,
        int b, int h, int s0, int t,
        const __half* __restrict__ Kh, const __half* __restrict__ Vh) {
    int row_lo = t >> 3;
    int c = t & 7;
    #pragma unroll
    for (int i = 0; i < 4; i++) {
        int arr = i >> 1;
        int row = ((i & 1) << 5) + row_lo;
        uint32_t dst = hbase + (uint32_t)(arr*9216 + row*144 + c*16);
        const __half* src = (arr == 0)
            ? Kh + ((size_t)(b*TT + s0 + row))*DD + h*64 + c*8
            : Vh + ((size_t)(b*DD + h*64 + row))*TT + s0 + c*8;
        CP_ASYNC16(dst, src);
    }
}

__global__ __launch_bounds__(256) void attn_mma_kernel(
        const __half* __restrict__ Qh,
        const __half* __restrict__ Kh, const __half* __restrict__ Vh,
        const float* __restrict__ gateq) {
    extern __shared__ char smc[];
    uint32_t sb = smem_to_u32(smc);
    int t = threadIdx.x;
    int w = t >> 5, lane = t & 31;
    int g = lane >> 2, tq = lane & 3;
    int bh = blockIdx.y;
    int b = bh >> 4, h = bh & 15;
    int t0 = blockIdx.x * 128;
    int trow = t0 + w*16 + g;

    int b_row  = lane & 7;
    int b_msel = (lane >> 4);
    int b_ksel = ((lane >> 3) & 1) * 8;

    uint32_t aqh[4][4];
    {
        size_t r0 = ((size_t)(b*TT + trow))*DD + h*64;
        size_t r8 = r0 + 8*(size_t)DD;
        #pragma unroll
        for (int kq = 0; kq < 4; kq++) {
            int c = kq*16 + tq*2;
            aqh[kq][0] = *(const uint32_t*)(Qh + r0 + c);
            aqh[kq][1] = *(const uint32_t*)(Qh + r8 + c);
            aqh[kq][2] = *(const uint32_t*)(Qh + r0 + c + 8);
            aqh[kq][3] = *(const uint32_t*)(Qh + r8 + c + 8);
        }
    }
    float gq0 = gateq[(size_t)bh*TT + trow];
    float gq1 = gateq[(size_t)bh*TT + trow + 8];

    float cacc[8][4];
    #pragma unroll
    for (int di = 0; di < 8; di++)
        #pragma unroll
        for (int r = 0; r < 4; r++) cacc[di][r] = 0.f;

    const int NCH = TT / 128;
    attn_load_half(sb,        b, h, 0,  t, Kh, Vh);
    attn_load_half(sb + HSTG, b, h, 64, t, Kh, Vh);
    CP_COMMIT();

    for (int ic = 0; ic < NCH; ic++) {
        CP_WAIT0();
        __syncthreads();
        if (ic + 1 < NCH) {
            uint32_t nbase = sb + (uint32_t)((ic+1) & 1) * ATTN_STG;
            attn_load_half(nbase,        b, h, (ic+1)*128,      t, Kh, Vh);
            attn_load_half(nbase + HSTG, b, h, (ic+1)*128 + 64, t, Kh, Vh);
            CP_COMMIT();
        }
        uint32_t stg = sb + (uint32_t)(ic & 1) * ATTN_STG;

        #pragma unroll
        for (int half = 0; half < 2; half++) {
            uint32_t uKh = stg + (uint32_t)half * HSTG;
            uint32_t uVh = uKh + 9216;

            // ---- GEMM1: S = Q . K^T ----
            float sacc[8][4];
            #pragma unroll
            for (int si = 0; si < 8; si++)
                #pragma unroll
                for (int r = 0; r < 4; r++) sacc[si][r] = 0.f;

            #pragma unroll
            for (int kk = 0; kk < 4; kk++) {
                uint32_t kfh[4][4];
                #pragma unroll
                for (int sp = 0; sp < 4; sp++) {
                    uint32_t off = (uint32_t)(((sp*2 + b_msel)*8 + b_row)*144 + (kk*16 + b_ksel)*2);
                    LDMX4(kfh[sp][0], kfh[sp][1], kfh[sp][2], kfh[sp][3], uKh + off);
                }
                #pragma unroll
                for (int sp = 0; sp < 4; sp++) {
                    MMA16816(sacc[2*sp],   aqh[kk][0], aqh[kk][1], aqh[kk][2], aqh[kk][3], kfh[sp][0], kfh[sp][1]);
                    MMA16816(sacc[2*sp+1], aqh[kk][0], aqh[kk][1], aqh[kk][2], aqh[kk][3], kfh[sp][2], kfh[sp][3]);
                }
            }

            // ---- modulation: fp32 sigmoid, fp16 pack ----
            uint32_t mh[4][4];
            #pragma unroll
            for (int j = 0; j < 4; j++) {
                #pragma unroll
                for (int hv = 0; hv < 2; hv++) {
                    int si = 2*j + hv;
                    float z00 = (sacc[si][0] - THRESH_C) * SHARP_C;
                    float z01 = (sacc[si][1] - THRESH_C) * SHARP_C;
                    float z10 = (sacc[si][2] - THRESH_C) * SHARP_C;
                    float z11 = (sacc[si][3] - THRESH_C) * SHARP_C;
                    float m00 = __fdividef(1.f, 1.f + __expf(-z00));
                    float m01 = __fdividef(1.f, 1.f + __expf(-z01));
                    float m10 = __fdividef(1.f, 1.f + __expf(-z10));
                    float m11 = __fdividef(1.f, 1.f + __expf(-z11));
                    mh[j][hv*2 + 0] = packh2(m00, m01);
                    mh[j][hv*2 + 1] = packh2(m10, m11);
                }
            }

            // ---- GEMM2: C += M . (gk*V) ----
            #pragma unroll
            for (int j = 0; j < 4; j++) {
                uint32_t vfh[4][4];
                #pragma unroll
                for (int dp = 0; dp < 4; dp++) {
                    uint32_t off = (uint32_t)(((dp*2 + b_msel)*8 + b_row)*144 + (j*16 + b_ksel)*2);
                    LDMX4(vfh[dp][0], vfh[dp][1], vfh[dp][2], vfh[dp][3], uVh + off);
                }
                #pragma unroll
                for (int dp = 0; dp < 4; dp++) {
                    MMA16816(cacc[2*dp],   mh[j][0], mh[j][1], mh[j][2], mh[j][3], vfh[dp][0], vfh[dp][1]);
                    MMA16816(cacc[2*dp+1], mh[j][0], mh[j][1], mh[j][2], mh[j][3], vfh[dp][2], vfh[dp][3]);
                }
            }
        }
    }

    // epilogue: apply gq, emit fp16 collapse
    size_t obase = ((size_t)(b*TT + trow))*DD + h*64;
    #pragma unroll
    for (int di = 0; di < 8; di++) {
        int col = di*8 + tq*2;
        float c00 = cacc[di][0]*gq0, c01 = cacc[di][1]*gq0;
        float c10 = cacc[di][2]*gq1, c11 = cacc[di][3]*gq1;
        *(uint32_t*)(g_ch + obase + col)                = packh2(c00, c01);
        *(uint32_t*)(g_ch + obase + 8*(size_t)DD + col) = packh2(c10, c11);
    }
}

// ================= launch =================
extern "C" void kernel_launch(void* const* d_in, const int* in_sizes, int n_in,
                              void* d_out, int out_size) {
    const float* x    = (const float*)d_in[0];
    const float* Wq   = (const float*)d_in[1];
    const float* Wk   = (const float*)d_in[2];
    const float* Wv   = (const float*)d_in[3];
    const float* gq   = (const float*)d_in[4];
    const float* gk   = (const float*)d_in[5];
    const float* Wo   = (const float*)d_in[6];
    const float* bo   = (const float*)d_in[7];
    const float* ln_w = (const float*)d_in[8];
    const float* ln_b = (const float*)d_in[9];
    float* out = (float*)d_out;

    float *p_gq, *p_gk;
    cudaGetSymbolAddress((void**)&p_gq, g_gateq);
    cudaGetSymbolAddress((void**)&p_gk, g_gatek);

    __half *p_vh, *p_qbh, *p_kbh, *p_vth;
    cudaGetSymbolAddress((void**)&p_vh,  g_vh);
    cudaGetSymbolAddress((void**)&p_qbh, g_qbh);
    cudaGetSymbolAddress((void**)&p_kbh, g_kbh);
    cudaGetSymbolAddress((void**)&p_vth, g_vth);

    cudaFuncSetAttribute(qkv_gemm, cudaFuncAttributeMaxDynamicSharedMemorySize, GEMM_SMEM_BYTES);
    cudaFuncSetAttribute(out_gemm, cudaFuncAttributeMaxDynamicSharedMemorySize, GEMM_SMEM_BYTES);
    cudaFuncSetAttribute(attn_mma_kernel, cudaFuncAttributeMaxDynamicSharedMemorySize, ATTN_SMEM);

    // 1. LayerNorm + fp16 conversions
    ln_kernel<<<NTOK, 256>>>(x, ln_w, ln_b);

    // 2. weight transpose (fp16), vectorized, z-indexed
    tsplit4_kernel<<<dim3(DD/32, DD/64, 4), 256>>>(Wq, Wk, Wv, Wo);

    // 3. fused QKV projections (fp16 outputs)
    qkv_gemm<<<dim3(GN/128, GM/128, 3), 256, GEMM_SMEM_BYTES>>>();

    // 4. normalize + gates (single-pass); V transpose
    norm_gate2_kernel<<<dim3((NTOK*HH)/8, 2), 256>>>(gq, gk);
    vtsplit_kernel<<<dim3(TT/32, DD/32, BB), 256>>>(p_vh, p_gk, p_vth);

    // 5. attention (fp32 sigmoid restored)
    attn_mma_kernel<<<dim3(TT/128, BB*HH), 256, ATTN_SMEM>>>(
        p_qbh, p_kbh, p_vth, p_gq);

    // 6. output projection
    out_gemm<<<dim3(GN/128, GM/128), 256, GEMM_SMEM_BYTES>>>(out, bo);
}